// round 1
// baseline (speedup 1.0000x reference)
#include <cuda_runtime.h>
#include <cuda_bf16.h>

// LSHGaussian: out[i,c] = sum_j exp(-0.5*||ref_i - ref_j||^2) * U[j,c]  -  U[i,c]
// N=16384, C=64, D=5.
// Attention-like tiled kernel, fp32 with packed f32x2 FMA (Blackwell FFMA2).

#define N_PTS 16384
#define C_CH  64
#define D_REF 5
#define BM    128     // rows per CTA
#define BN    128     // j-tile
#define TPB   256     // 2 threads per row (channel halves)

typedef unsigned long long u64;

__global__ __launch_bounds__(TPB, 1)
void lsh_gauss_kernel(const float* __restrict__ U,
                      const float* __restrict__ ref,
                      float* __restrict__ out)
{
    __shared__ float sU[BN * C_CH];    // 32 KB: U tile, row-major [BN][64]
    __shared__ float sR[BN * 6];       // per-j: rj[0..4] (raw), bias -0.5*L2E*|rj|^2

    const int tid       = threadIdx.x;
    const int row_local = tid & (BM - 1);
    const int half      = tid >> 7;             // 0: ch 0-31, 1: ch 32-63
    const int row       = blockIdx.x * BM + row_local;
    const float L2E     = 1.4426950408889634f;  // log2(e)

    // Per-thread query ref row, pre-scaled by log2(e), plus bias term.
    float ri[D_REF];
    float bi;
    {
        float s = 0.0f;
        #pragma unroll
        for (int k = 0; k < D_REF; ++k) {
            float v = ref[row * D_REF + k];
            ri[k] = v;
            s = fmaf(v, v, s);
        }
        bi = -0.5f * L2E * s;
        #pragma unroll
        for (int k = 0; k < D_REF; ++k) ri[k] *= L2E;
    }

    // 32 channels as 16 packed f32x2 accumulators.
    u64 acc[16];
    #pragma unroll
    for (int q = 0; q < 16; ++q) acc[q] = 0ull;

    for (int j0 = 0; j0 < N_PTS; j0 += BN) {
        __syncthreads();   // previous tile fully consumed before overwrite

        // Cooperative U tile load: 2048 float4, 8 per thread, coalesced.
        {
            const float4* gU = (const float4*)(U + j0 * C_CH);
            float4* s4 = (float4*)sU;
            #pragma unroll
            for (int q = 0; q < 8; ++q)
                s4[tid + q * TPB] = gU[tid + q * TPB];
        }
        // ref tile: one j per thread (first BN threads).
        if (tid < BN) {
            float r[D_REF];
            float s = 0.0f;
            #pragma unroll
            for (int k = 0; k < D_REF; ++k) {
                r[k] = ref[(j0 + tid) * D_REF + k];
                s = fmaf(r[k], r[k], s);
            }
            #pragma unroll
            for (int k = 0; k < D_REF; ++k) sR[tid * 6 + k] = r[k];
            sR[tid * 6 + 5] = -0.5f * L2E * s;
        }
        __syncthreads();

        // Base of this thread's 32-channel slice inside the tile (in u64 units).
        const u64* sUq = ((const u64*)sU) + half * 16;

        #pragma unroll 4
        for (int jj = 0; jj < BN; ++jj) {
            const float* rr = &sR[jj * 6];
            // t = log2(e) * (ri.rj - 0.5|ri|^2 - 0.5|rj|^2); exp arg clamp (d2>=0) => t<=0
            float t = bi + rr[5];
            #pragma unroll
            for (int k = 0; k < D_REF; ++k)
                t = fmaf(ri[k], rr[k], t);
            t = fminf(t, 0.0f);
            float w;
            asm("ex2.approx.ftz.f32 %0, %1;" : "=f"(w) : "f"(t));
            u64 w2;
            asm("mov.b64 %0, {%1, %1};" : "=l"(w2) : "f"(w));

            const ulonglong2* up = (const ulonglong2*)(sUq + (size_t)jj * 32);
            #pragma unroll
            for (int q = 0; q < 8; ++q) {
                ulonglong2 v = up[q];   // LDS.128, broadcast (conflict-free)
                asm("fma.rn.f32x2 %0, %1, %2, %0;" : "+l"(acc[2*q  ]) : "l"(w2), "l"(v.x));
                asm("fma.rn.f32x2 %0, %1, %2, %0;" : "+l"(acc[2*q+1]) : "l"(w2), "l"(v.y));
            }
        }
    }

    // Epilogue: out = acc - U (diagonal j==i carried weight exp(0)=1, matches K@U - U).
    {
        const float4* Urow = (const float4*)(U   + (size_t)row * C_CH + half * 32);
        float4*       Orow = (float4*)      (out + (size_t)row * C_CH + half * 32);
        #pragma unroll
        for (int q = 0; q < 8; ++q) {
            unsigned lo0, hi0, lo1, hi1;
            asm("mov.b64 {%0, %1}, %2;" : "=r"(lo0), "=r"(hi0) : "l"(acc[2*q  ]));
            asm("mov.b64 {%0, %1}, %2;" : "=r"(lo1), "=r"(hi1) : "l"(acc[2*q+1]));
            float4 u = Urow[q];
            float4 o;
            o.x = __uint_as_float(lo0) - u.x;
            o.y = __uint_as_float(hi0) - u.y;
            o.z = __uint_as_float(lo1) - u.z;
            o.w = __uint_as_float(hi1) - u.w;
            Orow[q] = o;
        }
    }
}

extern "C" void kernel_launch(void* const* d_in, const int* in_sizes, int n_in,
                              void* d_out, int out_size)
{
    const float* U   = (const float*)d_in[0];   // [N, 64]
    const float* ref = (const float*)d_in[1];   // [N, 5]
    float* out = (float*)d_out;                 // [N, 64]
    (void)in_sizes; (void)n_in; (void)out_size;

    lsh_gauss_kernel<<<N_PTS / BM, TPB>>>(U, ref, out);
}

// round 4
// speedup vs baseline: 3.8585x; 3.8585x over previous
#include <cuda_runtime.h>
#include <cstdint>

// LSHGaussian via legacy warp-level tf32 MMA (mma.sync.m16n8k8), since the
// bench toolchain targets sm_103 (no 'a') and tcgen05 won't assemble.
//   P[i,j] = exp(-0.5*||ref_i - ref_j||^2)  computed SIMT in fp32 directly in
//   the mma A-fragment register layout; D = P @ U with fp32 accumulation.
//   out = D - U.
// N=16384, C=64, D_ref=5. grid=128 CTAs x 256 threads (8 warps x 16 rows).

#define N_PTS  16384
#define CCH    64
#define BM     128
#define BK     128          // j-tile staged in smem
#define TPB    256
#define NTILES (N_PTS / BK)
#define USTR   72           // U-tile row stride in floats (72%32==8 -> conflict-free B loads)

__device__ __forceinline__ float ex2f(float x) {
    float r; asm("ex2.approx.ftz.f32 %0, %1;" : "=f"(r) : "f"(x)); return r;
}
__device__ __forceinline__ uint32_t cvt_tf32(float x) {
    uint32_t r; asm("cvt.rna.tf32.f32 %0, %1;" : "=r"(r) : "f"(x)); return r;
}

__global__ void __launch_bounds__(TPB, 1)
lsh_mma_kernel(const float* __restrict__ U, const float* __restrict__ ref,
               float* __restrict__ out)
{
    __shared__ uint32_t Us[BK * USTR];   // U tile, tf32-converted, [j][ch] stride 72
    __shared__ float    Rs[BK * 8];      // per-j: r0..r4, bias, pad, pad

    const int tid  = threadIdx.x;
    const int wid  = tid >> 5;
    const int lane = tid & 31;
    const int g    = lane >> 2;          // groupID: row-in-16 / n-in-8
    const int kin  = lane & 3;           // k-in-group
    const float L2E = 1.4426950408889634f;

    // Per-thread query rows: i_lo = g, i_hi = g+8 within this warp's 16-row block.
    const int rbase = blockIdx.x * BM + wid * 16;
    float ri_lo[5], ri_hi[5], bi_lo, bi_hi;
    {
        const float* rl = ref + (size_t)(rbase + g) * 5;
        const float* rh = ref + (size_t)(rbase + g + 8) * 5;
        float sl = 0.f, sh = 0.f;
        #pragma unroll
        for (int k = 0; k < 5; ++k) {
            float a = rl[k], b = rh[k];
            sl = fmaf(a, a, sl); sh = fmaf(b, b, sh);
            ri_lo[k] = a * L2E;  ri_hi[k] = b * L2E;
        }
        bi_lo = -0.5f * L2E * sl;
        bi_hi = -0.5f * L2E * sh;
    }

    // Accumulators: 8 n-tiles x 4 regs (m16n8 C fragment).
    float c[8][4];
    #pragma unroll
    for (int nt = 0; nt < 8; ++nt)
        #pragma unroll
        for (int q = 0; q < 4; ++q) c[nt][q] = 0.f;

    for (int t = 0; t < NTILES; ++t) {
        const int j0 = t * BK;
        __syncthreads();   // previous tile consumed

        // Stage U tile -> tf32 in smem, [j][ch], row stride 72.
        {
            const float4* Ug = (const float4*)(U + (size_t)j0 * CCH);
            #pragma unroll
            for (int it = 0; it < 8; ++it) {
                int f = it * TPB + tid;          // 0..2047 float4s
                int j = f >> 4, c4 = f & 15;
                float4 v = Ug[f];
                uint4 w;
                w.x = cvt_tf32(v.x); w.y = cvt_tf32(v.y);
                w.z = cvt_tf32(v.z); w.w = cvt_tf32(v.w);
                *(uint4*)&Us[j * USTR + c4 * 4] = w;
            }
        }
        // Stage ref tile: r0..r4, bias = -0.5*L2E*|rj|^2.
        if (tid < BK) {
            const float* rj = ref + (size_t)(j0 + tid) * 5;
            float r0 = rj[0], r1 = rj[1], r2 = rj[2], r3 = rj[3], r4 = rj[4];
            float s = fmaf(r0, r0, fmaf(r1, r1, fmaf(r2, r2, fmaf(r3, r3, r4 * r4))));
            float* R = &Rs[tid * 8];
            R[0] = r0; R[1] = r1; R[2] = r2; R[3] = r3;
            R[4] = r4; R[5] = -0.5f * L2E * s;
        }
        __syncthreads();

        #pragma unroll 4
        for (int kc = 0; kc < BK / 8; ++kc) {
            const int jA = kc * 8 + kin;     // this thread's k-lane j (a0/a1)
            const int jB = jA + 4;           // a2/a3

            // rj features (broadcast across n-groups, 4 distinct addrs, conflict-free)
            float4 rA0 = *(const float4*)&Rs[jA * 8];
            float4 rA1 = *(const float4*)&Rs[jA * 8 + 4];
            float4 rB0 = *(const float4*)&Rs[jB * 8];
            float4 rB1 = *(const float4*)&Rs[jB * 8 + 4];

            // 4 weights in A-fragment slots.
            float tLA = bi_lo + rA1.y, tHA = bi_hi + rA1.y;
            float tLB = bi_lo + rB1.y, tHB = bi_hi + rB1.y;
            tLA = fmaf(ri_lo[0], rA0.x, tLA); tHA = fmaf(ri_hi[0], rA0.x, tHA);
            tLB = fmaf(ri_lo[0], rB0.x, tLB); tHB = fmaf(ri_hi[0], rB0.x, tHB);
            tLA = fmaf(ri_lo[1], rA0.y, tLA); tHA = fmaf(ri_hi[1], rA0.y, tHA);
            tLB = fmaf(ri_lo[1], rB0.y, tLB); tHB = fmaf(ri_hi[1], rB0.y, tHB);
            tLA = fmaf(ri_lo[2], rA0.z, tLA); tHA = fmaf(ri_hi[2], rA0.z, tHA);
            tLB = fmaf(ri_lo[2], rB0.z, tLB); tHB = fmaf(ri_hi[2], rB0.z, tHB);
            tLA = fmaf(ri_lo[3], rA0.w, tLA); tHA = fmaf(ri_hi[3], rA0.w, tHA);
            tLB = fmaf(ri_lo[3], rB0.w, tLB); tHB = fmaf(ri_hi[3], rB0.w, tHB);
            tLA = fmaf(ri_lo[4], rA1.x, tLA); tHA = fmaf(ri_hi[4], rA1.x, tHA);
            tLB = fmaf(ri_lo[4], rB1.x, tLB); tHB = fmaf(ri_hi[4], rB1.x, tHB);

            uint32_t a0 = cvt_tf32(ex2f(fminf(tLA, 0.f)));
            uint32_t a1 = cvt_tf32(ex2f(fminf(tHA, 0.f)));
            uint32_t a2 = cvt_tf32(ex2f(fminf(tLB, 0.f)));
            uint32_t a3 = cvt_tf32(ex2f(fminf(tHB, 0.f)));

            // B fragments + MMA per n-tile. b0: (k=jA, n=nt*8+g), b1: (k=jB, ...)
            const uint32_t* uA = &Us[jA * USTR + g];
            const uint32_t* uB = &Us[jB * USTR + g];
            #pragma unroll
            for (int nt = 0; nt < 8; ++nt) {
                uint32_t b0 = uA[nt * 8];
                uint32_t b1 = uB[nt * 8];
                asm volatile(
                    "mma.sync.aligned.m16n8k8.row.col.f32.tf32.tf32.f32 "
                    "{%0,%1,%2,%3}, {%4,%5,%6,%7}, {%8,%9}, {%0,%1,%2,%3};"
                    : "+f"(c[nt][0]), "+f"(c[nt][1]), "+f"(c[nt][2]), "+f"(c[nt][3])
                    : "r"(a0), "r"(a1), "r"(a2), "r"(a3), "r"(b0), "r"(b1));
            }
        }
    }

    // Epilogue: out = C - U.  c0/c1 -> row g, cols 2*kin(+1); c2/c3 -> row g+8.
    {
        const int rl = rbase + g, rh = rl + 8;
        const int n0 = 2 * kin;
        #pragma unroll
        for (int nt = 0; nt < 8; ++nt) {
            const int col = nt * 8 + n0;
            float2 ul = *(const float2*)(U + (size_t)rl * CCH + col);
            float2 uh = *(const float2*)(U + (size_t)rh * CCH + col);
            float2 ol, oh;
            ol.x = c[nt][0] - ul.x; ol.y = c[nt][1] - ul.y;
            oh.x = c[nt][2] - uh.x; oh.y = c[nt][3] - uh.y;
            *(float2*)(out + (size_t)rl * CCH + col) = ol;
            *(float2*)(out + (size_t)rh * CCH + col) = oh;
        }
    }
}

extern "C" void kernel_launch(void* const* d_in, const int* in_sizes, int n_in,
                              void* d_out, int out_size)
{
    const float* U   = (const float*)d_in[0];   // [N, 64]
    const float* ref = (const float*)d_in[1];   // [N, 5]
    float* out = (float*)d_out;                 // [N, 64]
    (void)in_sizes; (void)n_in; (void)out_size;

    lsh_mma_kernel<<<N_PTS / BM, TPB>>>(U, ref, out);
}